// round 5
// baseline (speedup 1.0000x reference)
#include <cuda_runtime.h>
#include <cuda_bf16.h>
#include <cstdint>
#include <math.h>

// ---------------------------------------------------------------------------
// SimpleModelQ collapsed:
//   qk[b] = (M @ archi[b] + c) / sqrt(258),  M = kW^T qW, c = kW^T qb
//   (q.kb score shift is constant per batch -> cancels in softmax)
//   fbar[b] = softmax(qk[b].feats[b,s])-weighted mean of feats (255-dim)
//   res = vW@fbar+vb; h1=relu(W1@res+b1); h2=relu(W2@h1+b2); out=W3@h2+b3
// 5 launches: k0, attn(split-S + last-arriver merge), g1, g2, g3(+elected tail)
// ---------------------------------------------------------------------------

#define B_     128
#define S_     1024
#define LAST_  258
#define FEAT_  255

// ---- device scratch (zero-init at load) ----
__device__ float  g_qkp8[8 * 256 * 4];   // k0 partials [blk][f][{M0,M1,M2,c}]
__device__ float  g_u[256 * 256];        // per (b,half): unnormalized weighted sums
__device__ float2 g_ml[256];             // per (b,half): (m, l)
__device__ int    g_cntb[128];           // per-batch arrival counters (reset in-kernel)
__device__ int    g_cnt3;                // g3 arrival counter (reset in-kernel)
__device__ float  g_fbarT[256 * 128];    // k-major [f][b]; row 255 = 0 pad
__device__ float2 g_res2[512 * 128];     // res pairs: [k2][b] = (res[2k2],res[2k2+1])
__device__ float4 g_P4[2 * 128 * 128];   // h1 partials [ky][k4][b] packed 4-k
__device__ float2 g_h2[128 * 128];       // h2 pairs [k2][b]

__device__ __forceinline__ unsigned long long dup_f32(float a) {
    unsigned long long r;
    asm("mov.b64 %0, {%1, %1};" : "=l"(r) : "f"(a));
    return r;
}
__device__ __forceinline__ void fma_x2(unsigned long long& acc,
                                       unsigned long long a, unsigned long long w) {
    asm("fma.rn.f32x2 %0, %1, %2, %0;" : "+l"(acc) : "l"(a), "l"(w));
}
__device__ __forceinline__ void unpack_x2(unsigned long long v, float& lo, float& hi) {
    asm("mov.b64 {%0, %1}, %2;" : "=f"(lo), "=f"(hi) : "l"(v));
}

// ===========================================================================
// K0: partial M/c over a 128-h chunk. grid 8, block 256 (thread = feature f).
// ===========================================================================
__global__ void __launch_bounds__(256)
k0_kernel(const float* __restrict__ kW, const float* __restrict__ qW,
          const float* __restrict__ qb) {
    __shared__ float sw[128 * 4];
    const int f = threadIdx.x;
    const int h0 = blockIdx.x * 128;
    for (int j = f; j < 512; j += 256) {
        int h = h0 + (j >> 2), k = j & 3;
        sw[j] = (k < 3) ? qW[h * 3 + k] : qb[h];
    }
    __syncthreads();
    float m0 = 0.f, m1 = 0.f, m2 = 0.f, cc = 0.f;
    if (f < FEAT_) {
#pragma unroll 4
        for (int i = 0; i < 128; i++) {
            float kv = kW[(size_t)(h0 + i) * FEAT_ + f];
            m0 += kv * sw[i * 4 + 0];
            m1 += kv * sw[i * 4 + 1];
            m2 += kv * sw[i * 4 + 2];
            cc += kv * sw[i * 4 + 3];
        }
    }
    ((float4*)g_qkp8)[blockIdx.x * 256 + f] = make_float4(m0, m1, m2, cc);
}

// ===========================================================================
// Attention: 256 CTAs = (128 b) x (2 halves of S). 512 threads, 2 CTAs/SM.
// 16 chunks of 32 rows via cp.async.bulk, 3-stage mbarrier ring.
// Last-arriving CTA per batch merges the two halves' (m,l,u) -> fbar^T.
// ===========================================================================
#define ACH_   32
#define ANCH_  16
#define ACHB_  (ACH_ * LAST_ * 4)        // 33024 bytes, multiple of 16

// shared layout (floats)
#define A_BUF  0                          // 3 * 32*258 = 24768
#define A_QK   24768                      // 256
#define A_SC   (A_QK + 256)               // 32
#define A_PV   (A_SC + 32)                // 32
#define A_ST   (A_PV + 32)                // 4
#define A_MB   (A_ST + 4)                 // 8 (3 x u64 mbarriers; even offset)
#define A_FR   (A_MB + 8)                 // 4*256 = 1024
#define A_TOT  (A_FR + 1024)
#define A_SMEM_BYTES (A_TOT * 4)          // 104,528 B  (2 CTAs/SM fits 227KB)

__global__ void __launch_bounds__(512, 2)
attn_kernel(const float* __restrict__ input) {
    extern __shared__ float sm[];
    __shared__ int who;
    const int bh   = blockIdx.x;
    const int b    = bh >> 1;
    const int half = bh & 1;
    const int tid  = threadIdx.x;
    const uint32_t sb32 = (uint32_t)__cvta_generic_to_shared(sm);
    const uint32_t mb   = sb32 + A_MB * 4;
    const float* gbase = input + (size_t)b * S_ * LAST_;
    const float* hbase = gbase + (size_t)half * 512 * LAST_;

    if (tid == 0) {
#pragma unroll
        for (int s = 0; s < 3; s++)
            asm volatile("mbarrier.init.shared.b64 [%0], 1;" :: "r"(mb + s * 8) : "memory");
    }
    __syncthreads();

    auto issue = [&](int c) {
        if (tid == 0) {
            uint32_t bar = mb + (c % 3) * 8;
            uint32_t dst = sb32 + (uint32_t)((c % 3) * ACHB_);
            const float* g = hbase + (size_t)c * ACH_ * LAST_;
            asm volatile("mbarrier.arrive.expect_tx.shared.b64 _, [%0], %1;"
                         :: "r"(bar), "r"((uint32_t)ACHB_) : "memory");
            asm volatile("cp.async.bulk.shared::cta.global.mbarrier::complete_tx::bytes "
                         "[%0], [%1], %2, [%3];"
                         :: "r"(dst), "l"(g), "r"((uint32_t)ACHB_), "r"(bar) : "memory");
        }
    };
    issue(0);
    issue(1);

    // qk vector from k0 partials + this batch's archi
    const float a0 = gbase[FEAT_ + 0];
    const float a1 = gbase[FEAT_ + 1];
    const float a2 = gbase[FEAT_ + 2];
    if (tid < 256) {
        float4 s = make_float4(0.f, 0.f, 0.f, 0.f);
#pragma unroll
        for (int p = 0; p < 8; p++) {
            float4 v = ((const float4*)g_qkp8)[p * 256 + tid];
            s.x += v.x; s.y += v.y; s.z += v.z; s.w += v.w;
        }
        float val = (s.x * a0 + s.y * a1 + s.z * a2 + s.w) * rsqrtf(258.0f);
        if (tid >= FEAT_) val = 0.f;   // masks pad col 255 (archi col)
        sm[A_QK + tid] = val;
    }
    __syncthreads();

    const int sub = tid & 15, row = tid >> 4;   // scores: 16 thr/row, 32 rows
    const int c2  = tid & 127, grp = tid >> 7;  // fbar: col-pair x 4 groups of 8 rows

    float2 q2[8];
#pragma unroll
    for (int j = 0; j < 8; j++)
        q2[j] = *(const float2*)(sm + A_QK + j * 32 + sub * 2);

    float m_run = -INFINITY, l_run = 0.f;
    float2 acc = make_float2(0.f, 0.f);

    for (int c = 0; c < ANCH_; c++) {
        // wait chunk c
        {
            uint32_t bar = mb + (c % 3) * 8;
            uint32_t ph = (uint32_t)((c / 3) & 1);
            uint32_t done;
            asm volatile("{\n\t.reg .pred p;\n\t"
                         "mbarrier.try_wait.parity.acquire.cta.shared::cta.b64 p, [%1], %2;\n\t"
                         "selp.b32 %0, 1, 0, p;\n\t}"
                         : "=r"(done) : "r"(bar), "r"(ph) : "memory");
            if (!done) {
                asm volatile("{\n\t.reg .pred P1;\n\t"
                             "WL_%=:\n\t"
                             "mbarrier.try_wait.parity.acquire.cta.shared::cta.b64 P1, [%0], %1, 0x989680;\n\t"
                             "@P1 bra.uni WD_%=;\n\t"
                             "bra.uni WL_%=;\n\t"
                             "WD_%=:\n\t}"
                             :: "r"(bar), "r"(ph) : "memory");
            }
        }
        if (c + 2 < ANCH_) issue(c + 2);   // buffer freed by end-of-(c-1) sync

        const float* cur = sm + (c % 3) * ACH_ * LAST_;

        // scores
        {
            const float* rp = cur + row * LAST_;
            float v = 0.f;
#pragma unroll
            for (int j = 0; j < 8; j++) {
                float2 x = *(const float2*)(rp + j * 32 + sub * 2);
                v += x.x * q2[j].x + x.y * q2[j].y;
            }
            v += __shfl_xor_sync(0xffffffffu, v, 1);
            v += __shfl_xor_sync(0xffffffffu, v, 2);
            v += __shfl_xor_sync(0xffffffffu, v, 4);
            v += __shfl_xor_sync(0xffffffffu, v, 8);
            if (sub == 0) sm[A_SC + row] = v;
        }
        __syncthreads();

        // warp-0 register softmax over 32 scores
        if (tid < 32) {
            float s = sm[A_SC + tid];
            float mc = s;
#pragma unroll
            for (int o = 16; o; o >>= 1)
                mc = fmaxf(mc, __shfl_xor_sync(0xffffffffu, mc, o));
            float mnew  = fmaxf(m_run, mc);
            float alpha = __expf(m_run - mnew);
            float p = __expf(s - mnew);
            sm[A_PV + tid] = p;
            float ps = p;
#pragma unroll
            for (int o = 16; o; o >>= 1)
                ps += __shfl_xor_sync(0xffffffffu, ps, o);
            l_run = l_run * alpha + ps;
            m_run = mnew;
            if (tid == 0) sm[A_ST + 0] = alpha;
        }
        __syncthreads();

        // fbar accumulation
        {
            float alpha = sm[A_ST + 0];
            acc.x *= alpha; acc.y *= alpha;
            const float* fp = cur + c2 * 2;
#pragma unroll
            for (int j = 0; j < 8; j++) {
                int r = grp * 8 + j;
                float p = sm[A_PV + r];
                float2 x = *(const float2*)(fp + r * LAST_);
                acc.x += p * x.x; acc.y += p * x.y;
            }
        }
        __syncthreads();
    }

    // epilogue: reduce 4 group partials -> u, publish (m,l,u)
    *(float2*)(sm + A_FR + grp * 256 + c2 * 2) = acc;
    __syncthreads();
    if (tid < 256) {
        float uu = sm[A_FR + tid] + sm[A_FR + 256 + tid]
                 + sm[A_FR + 512 + tid] + sm[A_FR + 768 + tid];
        g_u[bh * 256 + tid] = (tid < FEAT_) ? uu : 0.f;
    }
    if (tid == 0) g_ml[bh] = make_float2(m_run, l_run);   // warp0 lane0 owns m,l
    __threadfence();
    __syncthreads();
    if (tid == 0) who = atomicAdd(&g_cntb[b], 1);
    __syncthreads();
    if (who == 1) {   // last arriver merges both halves
        __threadfence();
        float2 ml0 = g_ml[b * 2 + 0];
        float2 ml1 = g_ml[b * 2 + 1];
        float M  = fmaxf(ml0.x, ml1.x);
        float e0 = __expf(ml0.x - M);
        float e1 = __expf(ml1.x - M);
        float invL = 1.0f / (e0 * ml0.y + e1 * ml1.y);
        if (tid < 256) {
            float u0 = g_u[(b * 2 + 0) * 256 + tid];
            float u1 = g_u[(b * 2 + 1) * 256 + tid];
            g_fbarT[tid * 128 + b] = (e0 * u0 + e1 * u1) * invL;
        }
        if (tid == 0) g_cntb[b] = 0;   // reset for next replay
    }
}

// ===========================================================================
// g1: res = vW @ fbar + vb.  N=1024, K=256 (row 255 of fbarT is zero pad).
// grid 64 (16n x 128b tiles), 256 thr. Output packed pairs g_res2[k2][b].
// ===========================================================================
__global__ void __launch_bounds__(256)
g1_kernel(const float* __restrict__ vW, const float* __restrict__ vb) {
    __shared__ __align__(16) float Wt[32 * 16];
    const int tid  = threadIdx.x;
    const int b    = tid & 127;
    const int half = tid >> 7;
    const int n0   = blockIdx.x * 16;

    unsigned long long acc[4] = {0ull, 0ull, 0ull, 0ull};

    for (int k0 = 0; k0 < 256; k0 += 32) {
#pragma unroll
        for (int j = 0; j < 2; j++) {
            int e = tid + j * 256;
            int kk = e >> 4, nn = e & 15;
            int k = k0 + kk;
            Wt[kk * 16 + nn] = (k < FEAT_) ? vW[(size_t)(n0 + nn) * FEAT_ + k] : 0.f;
        }
        __syncthreads();
#pragma unroll
        for (int kk = 0; kk < 32; kk++) {
            float a = g_fbarT[(size_t)(k0 + kk) * 128 + b];
            unsigned long long ap = dup_f32(a);
            const unsigned long long* wr =
                (const unsigned long long*)&Wt[kk * 16 + half * 8];
#pragma unroll
            for (int i = 0; i < 4; i++) fma_x2(acc[i], ap, wr[i]);
        }
        __syncthreads();
    }
#pragma unroll
    for (int i = 0; i < 4; i++) {
        float lo, hi;
        unpack_x2(acc[i], lo, hi);
        int n = n0 + half * 8 + 2 * i;
        lo += vb[n]; hi += vb[n + 1];
        g_res2[(size_t)(n >> 1) * 128 + b] = make_float2(lo, hi);
    }
}

// ===========================================================================
// g2: h1 partials (no bias/relu yet), split-K2. N=512, K=1024.
// grid (64, 2): 8n x 128b tiles. Reads g_res2 pairs; writes g_P4 4-k packs.
// ===========================================================================
__global__ void __launch_bounds__(256)
g2_kernel(const float* __restrict__ W1) {
    __shared__ __align__(16) float Wt[32 * 8];
    const int tid  = threadIdx.x;
    const int b    = tid & 127;
    const int half = tid >> 7;
    const int n0   = blockIdx.x * 8;
    const int ky   = blockIdx.y;
    const int kbase = ky * 512;

    unsigned long long acc[2] = {0ull, 0ull};

    for (int s = 0; s < 16; s++) {
        int k0 = kbase + s * 32;
        {
            int kk = tid >> 3, nn = tid & 7;
            Wt[kk * 8 + nn] = W1[(size_t)(n0 + nn) * 1024 + k0 + kk];
        }
        __syncthreads();
#pragma unroll
        for (int kk2 = 0; kk2 < 16; kk2++) {
            float2 a2 = g_res2[(size_t)((k0 >> 1) + kk2) * 128 + b];
            unsigned long long ax = dup_f32(a2.x);
            unsigned long long ay = dup_f32(a2.y);
            const unsigned long long* w0 =
                (const unsigned long long*)&Wt[(2 * kk2 + 0) * 8 + half * 4];
            const unsigned long long* w1 =
                (const unsigned long long*)&Wt[(2 * kk2 + 1) * 8 + half * 4];
            fma_x2(acc[0], ax, w0[0]); fma_x2(acc[1], ax, w0[1]);
            fma_x2(acc[0], ay, w1[0]); fma_x2(acc[1], ay, w1[1]);
        }
        __syncthreads();
    }
    float4 o;
    unpack_x2(acc[0], o.x, o.y);
    unpack_x2(acc[1], o.z, o.w);
    g_P4[(size_t)(ky * 128 + (n0 >> 2) + half) * 128 + b] = o;
}

// ===========================================================================
// g3: h2 = relu(W2 @ relu(P0+P1+b1) + b2), then the LAST CTA computes
// out = W3 @ h2 + b3 (elected via atomic counter). grid 64 (4n tiles).
// ===========================================================================
__global__ void __launch_bounds__(256)
g3_kernel(const float* __restrict__ b1, const float* __restrict__ W2,
          const float* __restrict__ b2, const float* __restrict__ W3,
          const float* __restrict__ b3, float* __restrict__ out) {
    __shared__ __align__(16) float Wt[512 * 4];   // W2 tile [k][4n]
    __shared__ __align__(16) float b1s[512];
    __shared__ float w3s[512];
    __shared__ int who;
    const int tid  = threadIdx.x;
    const int b    = tid & 127;
    const int half = tid >> 7;
    const int n0   = blockIdx.x * 4;

#pragma unroll
    for (int j = 0; j < 8; j++) {
        int e = tid + j * 256;
        int kk = e >> 2, nn = e & 3;
        Wt[e] = W2[(size_t)(n0 + nn) * 512 + kk];
    }
    b1s[tid] = b1[tid];
    b1s[tid + 256] = b1[tid + 256];
    __syncthreads();

    unsigned long long acc = 0ull;
#pragma unroll 4
    for (int k4 = 0; k4 < 128; k4++) {
        float4 p0 = g_P4[(size_t)(0 * 128 + k4) * 128 + b];
        float4 p1 = g_P4[(size_t)(1 * 128 + k4) * 128 + b];
        const float4 bb = *(const float4*)&b1s[k4 * 4];
        float h0 = fmaxf(p0.x + p1.x + bb.x, 0.f);
        float h1 = fmaxf(p0.y + p1.y + bb.y, 0.f);
        float h2 = fmaxf(p0.z + p1.z + bb.z, 0.f);
        float h3 = fmaxf(p0.w + p1.w + bb.w, 0.f);
        const float* wr = &Wt[k4 * 16 + half * 2];
        fma_x2(acc, dup_f32(h0), *(const unsigned long long*)(wr + 0));
        fma_x2(acc, dup_f32(h1), *(const unsigned long long*)(wr + 4));
        fma_x2(acc, dup_f32(h2), *(const unsigned long long*)(wr + 8));
        fma_x2(acc, dup_f32(h3), *(const unsigned long long*)(wr + 12));
    }
    {
        float lo, hi;
        unpack_x2(acc, lo, hi);
        int n = n0 + half * 2;
        lo = fmaxf(lo + b2[n], 0.f);
        hi = fmaxf(hi + b2[n + 1], 0.f);
        g_h2[(size_t)(n >> 1) * 128 + b] = make_float2(lo, hi);
    }
    __threadfence();
    __syncthreads();
    if (tid == 0) who = atomicAdd(&g_cnt3, 1);
    __syncthreads();
    if (who == 63) {   // last CTA: final tiny layer
        __threadfence();
        w3s[tid] = W3[tid];
        w3s[tid + 256] = W3[tid + 256];
        __syncthreads();
        int j = tid >> 7;   // output index 0/1
        float a = b3[j];
#pragma unroll 8
        for (int k2 = 0; k2 < 128; k2++) {
            float2 h = g_h2[(size_t)k2 * 128 + b];
            a += h.x * w3s[j * 256 + 2 * k2] + h.y * w3s[j * 256 + 2 * k2 + 1];
        }
        out[b * 2 + j] = a;
        if (tid == 0) g_cnt3 = 0;   // reset for next replay
    }
}

// ===========================================================================
extern "C" void kernel_launch(void* const* d_in, const int* in_sizes, int n_in,
                              void* d_out, int out_size) {
    const float* input = (const float*)d_in[0];
    const float* kW = (const float*)d_in[1];
    // d_in[2] = kb: constant score shift per batch -> cancels in softmax
    const float* vW = (const float*)d_in[3];
    const float* vb = (const float*)d_in[4];
    const float* qW = (const float*)d_in[5];
    const float* qb = (const float*)d_in[6];
    const float* W1 = (const float*)d_in[7];
    const float* b1 = (const float*)d_in[8];
    const float* W2 = (const float*)d_in[9];
    const float* b2 = (const float*)d_in[10];
    const float* W3 = (const float*)d_in[11];
    const float* b3 = (const float*)d_in[12];
    float* out = (float*)d_out;

    cudaFuncSetAttribute(attn_kernel, cudaFuncAttributeMaxDynamicSharedMemorySize,
                         A_SMEM_BYTES);

    k0_kernel<<<8, 256>>>(kW, qW, qb);
    attn_kernel<<<256, 512, A_SMEM_BYTES>>>(input);
    g1_kernel<<<64, 256>>>(vW, vb);
    g2_kernel<<<dim3(64, 2), 256>>>(W1);
    g3_kernel<<<64, 256>>>(b1, W2, b2, W3, b3, out);
}

// round 6
// speedup vs baseline: 1.0997x; 1.0997x over previous
#include <cuda_runtime.h>
#include <cuda_bf16.h>
#include <cstdint>
#include <math.h>

// ---------------------------------------------------------------------------
// SimpleModelQ collapsed:
//   qk[b] = (M @ archi[b] + c) / sqrt(258),  M = kW^T qW, c = kW^T qb
//   (q.kb score shift is constant per batch -> cancels in softmax; kb unused)
//   fbar[b] = softmax(qk[b].feats[b,s])-weighted mean of feats (255-dim)
//   res = vW@fbar+vb; h1=relu(W1@res+b1); h2=relu(W2@h1+b2); out=W3@h2+b3
// 3 launches: k0 (+counter resets), attn (reg-resident, 4-way split-S),
//             mlp (single persistent kernel, internal grid syncs).
// ---------------------------------------------------------------------------

#define S_     1024
#define LAST_  258
#define FEAT_  255

// ---- device scratch (zero-init at load) ----
__device__ float  g_qkp8[8 * 256 * 4];   // k0 partials [blk][f][{M0,M1,M2,c}]
__device__ float  g_u[512 * 256];        // per (b,quarter) unnormalized sums
__device__ float2 g_ml[512];             // per (b,quarter) (m, l)
__device__ int    g_cntb[128];           // attn merge counters (reset by k0)
__device__ int    g_sync[8];             // mlp grid-sync counters (reset by k0)
__device__ float  g_fbarT[256 * 128];    // k-major [f][b]; row 255 stays 0
__device__ float  g_res[1024 * 128];     // res, n-major (= k-major for next layer)
__device__ float  g_P[4 * 512 * 128];    // h1 split-K partials
__device__ float  g_h1[512 * 128];
__device__ float  g_P2[4 * 256 * 128];   // h2 split-K partials
__device__ float  g_h2[256 * 128];

__device__ __forceinline__ unsigned long long dup_f32(float a) {
    unsigned long long r;
    asm("mov.b64 %0, {%1, %1};" : "=l"(r) : "f"(a));
    return r;
}
__device__ __forceinline__ void fma_x2(unsigned long long& acc,
                                       unsigned long long a, unsigned long long w) {
    asm("fma.rn.f32x2 %0, %1, %2, %0;" : "+l"(acc) : "l"(a), "l"(w));
}
__device__ __forceinline__ void mul_x2(unsigned long long& d, unsigned long long a,
                                       unsigned long long b) {
    asm("mul.rn.f32x2 %0, %1, %2;" : "=l"(d) : "l"(a), "l"(b));
}
__device__ __forceinline__ void unpack_x2(unsigned long long v, float& lo, float& hi) {
    asm("mov.b64 {%0, %1}, %2;" : "=f"(lo), "=f"(hi) : "l"(v));
}

// ===========================================================================
// K0: qk-projection partials over a 128-h chunk; block 0 also resets counters.
// ===========================================================================
__global__ void __launch_bounds__(256)
k0_kernel(const float* __restrict__ kW, const float* __restrict__ qW,
          const float* __restrict__ qb) {
    __shared__ float sw[128 * 4];
    const int f = threadIdx.x;
    const int h0 = blockIdx.x * 128;
    if (blockIdx.x == 0) {             // reset cross-kernel counters for this launch
        if (f < 128) g_cntb[f] = 0;
        else if (f < 136) g_sync[f - 128] = 0;
    }
    for (int j = f; j < 512; j += 256) {
        int h = h0 + (j >> 2), k = j & 3;
        sw[j] = (k < 3) ? qW[h * 3 + k] : qb[h];
    }
    __syncthreads();
    float m0 = 0.f, m1 = 0.f, m2 = 0.f, cc = 0.f;
    if (f < FEAT_) {
#pragma unroll 4
        for (int i = 0; i < 128; i++) {
            float kv = kW[(size_t)(h0 + i) * FEAT_ + f];
            m0 += kv * sw[i * 4 + 0];
            m1 += kv * sw[i * 4 + 1];
            m2 += kv * sw[i * 4 + 2];
            cc += kv * sw[i * 4 + 3];
        }
    }
    ((float4*)g_qkp8)[blockIdx.x * 256 + f] = make_float4(m0, m1, m2, cc);
}

// ===========================================================================
// Attention: 512 CTAs = (128 b) x (4 S-quarters of 256 rows), 256 threads.
// Per chunk of 32 rows: warp w loads rows w*4..w*4+3 (cols strided per lane)
// into REGISTERS, computes scores, and after softmax reuses the same
// registers for the fbar accumulation. Input read exactly once.
// ===========================================================================
__global__ void __launch_bounds__(256)
attn_kernel(const float* __restrict__ input) {
    __shared__ float qk[256];
    __shared__ float sc[32], pv[32], st[2];
    __shared__ float red[8 * 256];
    __shared__ int who;
    const int tid  = threadIdx.x;
    const int lane = tid & 31, w = tid >> 5;
    const int b = blockIdx.x >> 2, q = blockIdx.x & 3;
    const float* gbase = input + (size_t)b * S_ * LAST_;

    // qk vector = (sum of k0 partials) combined with this batch's archi
    {
        const float a0 = gbase[FEAT_ + 0];
        const float a1 = gbase[FEAT_ + 1];
        const float a2 = gbase[FEAT_ + 2];
        float4 s = make_float4(0.f, 0.f, 0.f, 0.f);
#pragma unroll
        for (int p = 0; p < 8; p++) {
            float4 v = ((const float4*)g_qkp8)[p * 256 + tid];
            s.x += v.x; s.y += v.y; s.z += v.z; s.w += v.w;
        }
        float val = (s.x * a0 + s.y * a1 + s.z * a2 + s.w) * rsqrtf(258.0f);
        qk[tid] = (tid < FEAT_) ? val : 0.f;   // masks archi col 255
    }
    __syncthreads();

    // lane covers cols {j*64 + lane*2, +1}, j = 0..3  (covers 0..255)
    unsigned long long q2[4];
#pragma unroll
    for (int j = 0; j < 4; j++)
        q2[j] = *(const unsigned long long*)(qk + j * 64 + lane * 2);

    float m_run = -INFINITY, l_run = 0.f;   // live in warp-0 registers
    unsigned long long acc[4] = {0ull, 0ull, 0ull, 0ull};

    const float* pbase = gbase + (size_t)(q * 256) * LAST_ + lane * 2;

    for (int c = 0; c < 8; c++) {
        // ---- load 4 rows x 8 cols into registers (coalesced LDG.64) ----
        unsigned long long xr[4][4];
        const float* rp = pbase + (size_t)(c * 32 + w * 4) * LAST_;
#pragma unroll
        for (int i = 0; i < 4; i++)
#pragma unroll
            for (int j = 0; j < 4; j++)
                xr[i][j] = *(const unsigned long long*)(rp + (size_t)i * LAST_ + j * 64);

        // ---- scores (f32x2 dot + warp reduce) ----
        float v[4];
#pragma unroll
        for (int i = 0; i < 4; i++) {
            unsigned long long va = 0ull;
#pragma unroll
            for (int j = 0; j < 4; j++) fma_x2(va, xr[i][j], q2[j]);
            float lo, hi; unpack_x2(va, lo, hi);
            v[i] = lo + hi;
        }
#pragma unroll
        for (int o = 16; o; o >>= 1) {
#pragma unroll
            for (int i = 0; i < 4; i++)
                v[i] += __shfl_xor_sync(0xffffffffu, v[i], o);
        }
        if (lane == 0) {
#pragma unroll
            for (int i = 0; i < 4; i++) sc[w * 4 + i] = v[i];
        }
        __syncthreads();

        // ---- warp-0 register softmax over 32 scores ----
        if (tid < 32) {
            float s = sc[tid];
            float mc = s;
#pragma unroll
            for (int o = 16; o; o >>= 1)
                mc = fmaxf(mc, __shfl_xor_sync(0xffffffffu, mc, o));
            float mnew  = fmaxf(m_run, mc);
            float alpha = __expf(m_run - mnew);
            float p = __expf(s - mnew);
            pv[tid] = p;
            float ps = p;
#pragma unroll
            for (int o = 16; o; o >>= 1)
                ps += __shfl_xor_sync(0xffffffffu, ps, o);
            l_run = l_run * alpha + ps;
            m_run = mnew;
            if (tid == 0) st[0] = alpha;
        }
        __syncthreads();

        // ---- fbar accumulation, reusing xr registers ----
        {
            unsigned long long ap = dup_f32(st[0]);
#pragma unroll
            for (int j = 0; j < 4; j++) mul_x2(acc[j], acc[j], ap);
#pragma unroll
            for (int i = 0; i < 4; i++) {
                unsigned long long pp = dup_f32(pv[w * 4 + i]);
#pragma unroll
                for (int j = 0; j < 4; j++) fma_x2(acc[j], pp, xr[i][j]);
            }
        }
        __syncthreads();   // protect sc/pv for next chunk
    }

    // ---- epilogue: cross-warp reduce -> (m, l, u); 4-way last-arriver merge ----
#pragma unroll
    for (int j = 0; j < 4; j++)
        *(unsigned long long*)(red + w * 256 + j * 64 + lane * 2) = acc[j];
    if (tid == 0) { st[0] = m_run; st[1] = l_run; }
    __syncthreads();
    {
        float u = 0.f;
#pragma unroll
        for (int ww = 0; ww < 8; ww++) u += red[ww * 256 + tid];
        g_u[(size_t)blockIdx.x * 256 + tid] = u;
        if (tid == 0) g_ml[blockIdx.x] = make_float2(st[0], st[1]);
    }
    __threadfence();
    __syncthreads();
    if (tid == 0) who = atomicAdd(&g_cntb[b], 1);
    __syncthreads();
    if (who == 3) {
        __threadfence();
        float2 ml[4];
        float M = -INFINITY;
#pragma unroll
        for (int qq = 0; qq < 4; qq++) {
            ml[qq] = g_ml[b * 4 + qq];
            M = fmaxf(M, ml[qq].x);
        }
        float e[4], L = 0.f;
#pragma unroll
        for (int qq = 0; qq < 4; qq++) {
            e[qq] = __expf(ml[qq].x - M);
            L += e[qq] * ml[qq].y;
        }
        float invL = 1.0f / L;
        if (tid < FEAT_) {
            float uu = 0.f;
#pragma unroll
            for (int qq = 0; qq < 4; qq++)
                uu += e[qq] * g_u[(size_t)(b * 4 + qq) * 256 + tid];
            g_fbarT[tid * 128 + b] = uu * invL;
        }
    }
}

// ===========================================================================
// MLP: single persistent kernel. 128 CTAs (all co-resident on 148 SMs ->
// grid sync via atomic counters is safe), 256 threads.
// ===========================================================================
__device__ __forceinline__ void grid_sync(int idx) {
    __syncthreads();
    if (threadIdx.x == 0) {
        __threadfence();
        atomicAdd(&g_sync[idx], 1);
        while (*(volatile int*)&g_sync[idx] < 128) { }
    }
    __syncthreads();
}

__global__ void __launch_bounds__(256)
mlp_kernel(const float* __restrict__ vW, const float* __restrict__ vb,
           const float* __restrict__ W1, const float* __restrict__ b1,
           const float* __restrict__ W2, const float* __restrict__ b2,
           const float* __restrict__ W3, const float* __restrict__ b3,
           float* __restrict__ out) {
    __shared__ float smw[256 * 18];   // bank-padded W tiles, reused per phase
    const int tid = threadIdx.x;
    const int c   = blockIdx.x;
    const int b   = tid & 127, h = tid >> 7;

    // ---------- phase 1: res = vW @ fbar + vb  (CTA: 8 n, K=256 incl pad) ----
    {
        const int n0 = c * 8;
#pragma unroll
        for (int nn = 0; nn < 8; nn++)
            smw[tid * 10 + nn] = (tid < FEAT_) ? vW[(size_t)(n0 + nn) * FEAT_ + tid] : 0.f;
        __syncthreads();
        unsigned long long acc[2] = {0ull, 0ull};
#pragma unroll 8
        for (int kk = 0; kk < 256; kk++) {
            unsigned long long ap = dup_f32(g_fbarT[kk * 128 + b]);
            const float* wp = &smw[kk * 10 + h * 4];
            fma_x2(acc[0], ap, *(const unsigned long long*)(wp + 0));
            fma_x2(acc[1], ap, *(const unsigned long long*)(wp + 2));
        }
#pragma unroll
        for (int i = 0; i < 2; i++) {
            float lo, hi; unpack_x2(acc[i], lo, hi);
            int n = n0 + h * 4 + 2 * i;
            g_res[(size_t)n * 128 + b]       = lo + vb[n];
            g_res[(size_t)(n + 1) * 128 + b] = hi + vb[n + 1];
        }
    }
    grid_sync(0);

    // ---------- phase 2: h1 partials (16n x 256k tiles, 4-way split-K) ----
    {
        const int n0 = (c >> 2) * 16, k0 = (c & 3) * 256, ks = c & 3;
#pragma unroll
        for (int nn = 0; nn < 16; nn++)
            smw[tid * 18 + nn] = W1[(size_t)(n0 + nn) * 1024 + k0 + tid];
        __syncthreads();
        unsigned long long acc[4] = {0ull, 0ull, 0ull, 0ull};
#pragma unroll 8
        for (int kk = 0; kk < 256; kk++) {
            unsigned long long ap = dup_f32(g_res[(size_t)(k0 + kk) * 128 + b]);
            const float* wp = &smw[kk * 18 + h * 8];
            fma_x2(acc[0], ap, *(const unsigned long long*)(wp + 0));
            fma_x2(acc[1], ap, *(const unsigned long long*)(wp + 2));
            fma_x2(acc[2], ap, *(const unsigned long long*)(wp + 4));
            fma_x2(acc[3], ap, *(const unsigned long long*)(wp + 6));
        }
#pragma unroll
        for (int i = 0; i < 4; i++) {
            float lo, hi; unpack_x2(acc[i], lo, hi);
            int n = n0 + h * 8 + 2 * i;
            g_P[(size_t)(ks * 512 + n) * 128 + b]     = lo;
            g_P[(size_t)(ks * 512 + n + 1) * 128 + b] = hi;
        }
    }
    grid_sync(1);

    // ---------- phase 2.5: h1 = relu(sum_ks P + b1) ----
    if (tid < 128) {
        int idx = c * 128 + tid;                    // 16384 float4 total
        const float4* P4 = (const float4*)g_P;
        float4 s0 = P4[idx], s1 = P4[16384 + idx];
        float4 s2 = P4[32768 + idx], s3 = P4[49152 + idx];
        float bb = b1[idx >> 5];
        float4 r;
        r.x = fmaxf(s0.x + s1.x + s2.x + s3.x + bb, 0.f);
        r.y = fmaxf(s0.y + s1.y + s2.y + s3.y + bb, 0.f);
        r.z = fmaxf(s0.z + s1.z + s2.z + s3.z + bb, 0.f);
        r.w = fmaxf(s0.w + s1.w + s2.w + s3.w + bb, 0.f);
        ((float4*)g_h1)[idx] = r;
    }
    grid_sync(2);

    // ---------- phase 3: h2 partials (8n x 128k tiles, 4-way split-K) ----
    {
        const int n0 = (c >> 2) * 8, k0 = (c & 3) * 128, ks = c & 3;
        if (tid < 128) {
#pragma unroll
            for (int nn = 0; nn < 8; nn++)
                smw[tid * 10 + nn] = W2[(size_t)(n0 + nn) * 512 + k0 + tid];
        }
        __syncthreads();
        unsigned long long acc[2] = {0ull, 0ull};
#pragma unroll 8
        for (int kk = 0; kk < 128; kk++) {
            unsigned long long ap = dup_f32(g_h1[(size_t)(k0 + kk) * 128 + b]);
            const float* wp = &smw[kk * 10 + h * 4];
            fma_x2(acc[0], ap, *(const unsigned long long*)(wp + 0));
            fma_x2(acc[1], ap, *(const unsigned long long*)(wp + 2));
        }
#pragma unroll
        for (int i = 0; i < 2; i++) {
            float lo, hi; unpack_x2(acc[i], lo, hi);
            int n = n0 + h * 4 + 2 * i;
            g_P2[(size_t)(ks * 256 + n) * 128 + b]     = lo;
            g_P2[(size_t)(ks * 256 + n + 1) * 128 + b] = hi;
        }
    }
    grid_sync(3);

    // ---------- phase 3.5: h2 = relu(sum_ks P2 + b2) ----
    if (tid < 64) {
        int idx = c * 64 + tid;                     // 8192 float4 total
        const float4* P4 = (const float4*)g_P2;
        float4 s0 = P4[idx], s1 = P4[8192 + idx];
        float4 s2 = P4[16384 + idx], s3 = P4[24576 + idx];
        float bb = b2[idx >> 5];
        float4 r;
        r.x = fmaxf(s0.x + s1.x + s2.x + s3.x + bb, 0.f);
        r.y = fmaxf(s0.y + s1.y + s2.y + s3.y + bb, 0.f);
        r.z = fmaxf(s0.z + s1.z + s2.z + s3.z + bb, 0.f);
        r.w = fmaxf(s0.w + s1.w + s2.w + s3.w + bb, 0.f);
        ((float4*)g_h2)[idx] = r;
    }
    grid_sync(4);

    // ---------- phase 4: final 2-wide layer, CTA 0 only ----
    if (c == 0) {
        smw[tid]       = W3[tid];
        smw[256 + tid] = W3[256 + tid];
        __syncthreads();
        if (tid < 128) {
            float a0 = 0.f, a1 = 0.f;
#pragma unroll 8
            for (int k = 0; k < 256; k++) {
                float hh = g_h2[k * 128 + tid];
                a0 += hh * smw[k];
                a1 += hh * smw[256 + k];
            }
            ((float2*)out)[tid] = make_float2(a0 + b3[0], a1 + b3[1]);
        }
    }
}

// ===========================================================================
extern "C" void kernel_launch(void* const* d_in, const int* in_sizes, int n_in,
                              void* d_out, int out_size) {
    const float* input = (const float*)d_in[0];
    const float* kW = (const float*)d_in[1];
    // d_in[2] = kb: constant score shift per batch -> cancels in softmax
    const float* vW = (const float*)d_in[3];
    const float* vb = (const float*)d_in[4];
    const float* qW = (const float*)d_in[5];
    const float* qb = (const float*)d_in[6];
    const float* W1 = (const float*)d_in[7];
    const float* b1 = (const float*)d_in[8];
    const float* W2 = (const float*)d_in[9];
    const float* b2 = (const float*)d_in[10];
    const float* W3 = (const float*)d_in[11];
    const float* b3 = (const float*)d_in[12];
    float* out = (float*)d_out;

    k0_kernel<<<8, 256>>>(kW, qW, qb);
    attn_kernel<<<512, 256>>>(input);
    mlp_kernel<<<128, 256>>>(vW, vb, W1, b1, W2, b2, W3, b3, out);
}

// round 7
// speedup vs baseline: 1.4255x; 1.2962x over previous
#include <cuda_runtime.h>
#include <cuda_bf16.h>
#include <cstdint>
#include <math.h>

// ---------------------------------------------------------------------------
// SimpleModelQ collapsed:
//   qk[b] = (M @ archi[b] + c) / sqrt(258),  M = kW^T qW, c = kW^T qb
//   (q.kb score shift is constant per batch -> cancels in softmax; kb unused)
//   fbar[b] = softmax(qk[b].feats[b,s])-weighted mean of feats (255-dim)
//   res = vW@fbar+vb; h1=relu(W1@res+b1); h2=relu(W2@h1+b2); out=W3@h2+b3
// 3 launches: k0 (64 CTAs + elected merge), attn (warp-local softmax,
// barrier-free mainloop, 2-way split-S), mlp (persistent, grid syncs).
// ---------------------------------------------------------------------------

#define S_     1024
#define LAST_  258
#define FEAT_  255

// ---- device scratch (zero-init at load) ----
__device__ float4 g_qkp64[64 * 256];     // k0 partials [blk][f]
__device__ float4 g_qkpF[256];           // merged {M0,M1,M2,c} per feature
__device__ int    g_cntk;                // k0 merge counter (self-resetting)
__device__ float  g_u[256 * 256];        // per (b,half) unnormalized sums
__device__ float2 g_ml[256];             // per (b,half) (m, l)
__device__ int    g_cntb[128];           // attn merge counters (reset by k0)
__device__ int    g_sync[8];             // mlp grid-sync counters (reset by k0)
__device__ float  g_fbarT[256 * 128];    // k-major [f][b]
__device__ float  g_res[1024 * 128];
__device__ float  g_P[4 * 512 * 128];
__device__ float  g_h1[512 * 128];
__device__ float  g_P2[4 * 256 * 128];
__device__ float  g_h2[256 * 128];

__device__ __forceinline__ unsigned long long dup_f32(float a) {
    unsigned long long r;
    asm("mov.b64 %0, {%1, %1};" : "=l"(r) : "f"(a));
    return r;
}
__device__ __forceinline__ void fma_x2(unsigned long long& acc,
                                       unsigned long long a, unsigned long long w) {
    asm("fma.rn.f32x2 %0, %1, %2, %0;" : "+l"(acc) : "l"(a), "l"(w));
}
__device__ __forceinline__ void mul_x2(unsigned long long& d, unsigned long long a,
                                       unsigned long long b) {
    asm("mul.rn.f32x2 %0, %1, %2;" : "=l"(d) : "l"(a), "l"(b));
}
__device__ __forceinline__ void unpack_x2(unsigned long long v, float& lo, float& hi) {
    asm("mov.b64 {%0, %1}, %2;" : "=f"(lo), "=f"(hi) : "l"(v));
}

// ===========================================================================
// K0: 64 CTAs x 16-h chunks, fully unrolled loads (MLP~16). Last-arriving
// CTA merges the 64 partials into g_qkpF. Block 0 resets downstream counters.
// ===========================================================================
__global__ void __launch_bounds__(256)
k0_kernel(const float* __restrict__ kW, const float* __restrict__ qW,
          const float* __restrict__ qb) {
    __shared__ float sw[16 * 4];
    __shared__ int who;
    const int f = threadIdx.x;
    const int h0 = blockIdx.x * 16;
    if (blockIdx.x == 0) {
        if (f < 128) g_cntb[f] = 0;
        else if (f < 136) g_sync[f - 128] = 0;
    }
    if (f < 64) {
        int h = h0 + (f >> 2), k = f & 3;
        sw[f] = (k < 3) ? qW[h * 3 + k] : qb[h];
    }
    __syncthreads();
    float m0 = 0.f, m1 = 0.f, m2 = 0.f, cc = 0.f;
    if (f < FEAT_) {
#pragma unroll
        for (int i = 0; i < 16; i++) {
            float kv = kW[(size_t)(h0 + i) * FEAT_ + f];
            m0 += kv * sw[i * 4 + 0];
            m1 += kv * sw[i * 4 + 1];
            m2 += kv * sw[i * 4 + 2];
            cc += kv * sw[i * 4 + 3];
        }
    }
    g_qkp64[blockIdx.x * 256 + f] = make_float4(m0, m1, m2, cc);
    __threadfence();
    __syncthreads();
    if (f == 0) who = atomicAdd(&g_cntk, 1);
    __syncthreads();
    if (who == 63) {
        __threadfence();
        float4 s = make_float4(0.f, 0.f, 0.f, 0.f);
#pragma unroll 8
        for (int p = 0; p < 64; p++) {
            float4 v = g_qkp64[p * 256 + f];
            s.x += v.x; s.y += v.y; s.z += v.z; s.w += v.w;
        }
        g_qkpF[f] = s;
        if (f == 0) g_cntk = 0;   // reset for next replay
    }
}

// ===========================================================================
// Attention: 256 CTAs = (128 b) x (2 S-halves of 512 rows), 256 threads.
// Warp-local online softmax: each warp owns rows w*4..w*4+3 of every 32-row
// chunk; scores are warp-broadcast after shuffle reduce, so softmax state
// (m,l,alpha,p) is computed redundantly per lane. NO barriers in the loop.
// 2-chunk register double buffer hides load latency behind compute.
// ===========================================================================
__global__ void __launch_bounds__(256, 2)
attn_kernel(const float* __restrict__ input) {
    __shared__ float qk[256];
    __shared__ float red[8 * 256];
    __shared__ float2 mlw[8];
    __shared__ int who;
    const int tid  = threadIdx.x;
    const int lane = tid & 31, w = tid >> 5;
    const int b = blockIdx.x >> 1, half = blockIdx.x & 1;
    const float* gbase = input + (size_t)b * S_ * LAST_;

    // qk vector from merged projection params + this batch's archi
    {
        const float a0 = gbase[FEAT_ + 0];
        const float a1 = gbase[FEAT_ + 1];
        const float a2 = gbase[FEAT_ + 2];
        float4 pr = g_qkpF[tid];
        float val = (pr.x * a0 + pr.y * a1 + pr.z * a2 + pr.w) * rsqrtf(258.0f);
        qk[tid] = (tid < FEAT_) ? val : 0.f;
    }
    __syncthreads();

    unsigned long long q2[4];
#pragma unroll
    for (int j = 0; j < 4; j++)
        q2[j] = *(const unsigned long long*)(qk + j * 64 + lane * 2);

    const float* pbase = gbase + (size_t)(half * 512) * LAST_ + lane * 2;

    float m_w = -INFINITY, l_w = 0.f;
    unsigned long long acc[4] = {0ull, 0ull, 0ull, 0ull};
    unsigned long long xA[4][4], xB[4][4];

    auto loadc = [&](unsigned long long (&x)[4][4], int c) {
        const float* rp = pbase + (size_t)(c * 32 + w * 4) * LAST_;
#pragma unroll
        for (int i = 0; i < 4; i++)
#pragma unroll
            for (int j = 0; j < 4; j++)
                x[i][j] = *(const unsigned long long*)(rp + (size_t)i * LAST_ + j * 64);
    };
    auto process = [&](unsigned long long (&x)[4][4]) {
        float v[4];
#pragma unroll
        for (int i = 0; i < 4; i++) {
            unsigned long long va = 0ull;
#pragma unroll
            for (int j = 0; j < 4; j++) fma_x2(va, x[i][j], q2[j]);
            float lo, hi; unpack_x2(va, lo, hi);
            v[i] = lo + hi;
        }
#pragma unroll
        for (int o = 16; o; o >>= 1) {
#pragma unroll
            for (int i = 0; i < 4; i++)
                v[i] += __shfl_xor_sync(0xffffffffu, v[i], o);
        }
        // v[i] identical in all lanes -> warp-local softmax, no smem
        float mc = fmaxf(fmaxf(v[0], v[1]), fmaxf(v[2], v[3]));
        float mnew  = fmaxf(m_w, mc);
        float alpha = __expf(m_w - mnew);
        float p0 = __expf(v[0] - mnew), p1 = __expf(v[1] - mnew);
        float p2 = __expf(v[2] - mnew), p3 = __expf(v[3] - mnew);
        l_w = l_w * alpha + (p0 + p1) + (p2 + p3);
        m_w = mnew;
        unsigned long long ap = dup_f32(alpha);
#pragma unroll
        for (int j = 0; j < 4; j++) mul_x2(acc[j], acc[j], ap);
        unsigned long long pp0 = dup_f32(p0), pp1 = dup_f32(p1);
        unsigned long long pp2 = dup_f32(p2), pp3 = dup_f32(p3);
#pragma unroll
        for (int j = 0; j < 4; j++) {
            fma_x2(acc[j], pp0, x[0][j]);
            fma_x2(acc[j], pp1, x[1][j]);
            fma_x2(acc[j], pp2, x[2][j]);
            fma_x2(acc[j], pp3, x[3][j]);
        }
    };

    loadc(xA, 0);
    for (int cc = 0; cc < 8; cc++) {
        int c0 = 2 * cc;
        loadc(xB, c0 + 1);
        process(xA);
        if (cc < 7) loadc(xA, c0 + 2);
        process(xB);
    }

    // ---- epilogue: merge 8 warps' (m,l,acc) in smem frame ----
#pragma unroll
    for (int j = 0; j < 4; j++)
        *(unsigned long long*)(red + w * 256 + j * 64 + lane * 2) = acc[j];
    if (lane == 0) mlw[w] = make_float2(m_w, l_w);
    __syncthreads();
    {
        float M = -INFINITY;
#pragma unroll
        for (int ww = 0; ww < 8; ww++) M = fmaxf(M, mlw[ww].x);
        float L = 0.f, u = 0.f;
#pragma unroll
        for (int ww = 0; ww < 8; ww++) {
            float e = __expf(mlw[ww].x - M);
            L += e * mlw[ww].y;
            u += e * red[ww * 256 + tid];
        }
        g_u[(size_t)blockIdx.x * 256 + tid] = u;
        if (tid == 0) g_ml[blockIdx.x] = make_float2(M, L);
    }
    __threadfence();
    __syncthreads();
    if (tid == 0) who = atomicAdd(&g_cntb[b], 1);
    __syncthreads();
    if (who == 1) {   // last arriver merges the two halves
        __threadfence();
        float2 ml0 = g_ml[b * 2 + 0];
        float2 ml1 = g_ml[b * 2 + 1];
        float M  = fmaxf(ml0.x, ml1.x);
        float e0 = __expf(ml0.x - M);
        float e1 = __expf(ml1.x - M);
        float invL = 1.0f / (e0 * ml0.y + e1 * ml1.y);
        if (tid < FEAT_) {
            float u0 = g_u[(size_t)(b * 2 + 0) * 256 + tid];
            float u1 = g_u[(size_t)(b * 2 + 1) * 256 + tid];
            g_fbarT[tid * 128 + b] = (e0 * u0 + e1 * u1) * invL;
        }
    }
}

// ===========================================================================
// MLP: single persistent kernel. 128 CTAs (all co-resident), 256 threads.
// ===========================================================================
__device__ __forceinline__ void grid_sync(int idx) {
    __syncthreads();
    if (threadIdx.x == 0) {
        __threadfence();
        atomicAdd(&g_sync[idx], 1);
        while (*(volatile int*)&g_sync[idx] < 128) { }
    }
    __syncthreads();
}

__global__ void __launch_bounds__(256)
mlp_kernel(const float* __restrict__ vW, const float* __restrict__ vb,
           const float* __restrict__ W1, const float* __restrict__ b1,
           const float* __restrict__ W2, const float* __restrict__ b2,
           const float* __restrict__ W3, const float* __restrict__ b3,
           float* __restrict__ out) {
    __shared__ float smw[256 * 18];
    const int tid = threadIdx.x;
    const int c   = blockIdx.x;
    const int b   = tid & 127, h = tid >> 7;

    // ---------- phase 1: res = vW @ fbar + vb  (8 n per CTA, K=256) ----
    {
        const int n0 = c * 8;
#pragma unroll
        for (int nn = 0; nn < 8; nn++)
            smw[tid * 10 + nn] = (tid < FEAT_) ? vW[(size_t)(n0 + nn) * FEAT_ + tid] : 0.f;
        __syncthreads();
        unsigned long long acc[2] = {0ull, 0ull};
#pragma unroll 16
        for (int kk = 0; kk < 256; kk++) {
            unsigned long long ap = dup_f32(g_fbarT[kk * 128 + b]);
            const float* wp = &smw[kk * 10 + h * 4];
            fma_x2(acc[0], ap, *(const unsigned long long*)(wp + 0));
            fma_x2(acc[1], ap, *(const unsigned long long*)(wp + 2));
        }
#pragma unroll
        for (int i = 0; i < 2; i++) {
            float lo, hi; unpack_x2(acc[i], lo, hi);
            int n = n0 + h * 4 + 2 * i;
            g_res[(size_t)n * 128 + b]       = lo + vb[n];
            g_res[(size_t)(n + 1) * 128 + b] = hi + vb[n + 1];
        }
    }
    grid_sync(0);

    // ---------- phase 2: h1 partials (16n x 256k, 4-way split-K) ----
    {
        const int n0 = (c >> 2) * 16, k0 = (c & 3) * 256, ks = c & 3;
#pragma unroll
        for (int nn = 0; nn < 16; nn++)
            smw[tid * 18 + nn] = W1[(size_t)(n0 + nn) * 1024 + k0 + tid];
        __syncthreads();
        unsigned long long acc[4] = {0ull, 0ull, 0ull, 0ull};
#pragma unroll 16
        for (int kk = 0; kk < 256; kk++) {
            unsigned long long ap = dup_f32(g_res[(size_t)(k0 + kk) * 128 + b]);
            const float* wp = &smw[kk * 18 + h * 8];
            fma_x2(acc[0], ap, *(const unsigned long long*)(wp + 0));
            fma_x2(acc[1], ap, *(const unsigned long long*)(wp + 2));
            fma_x2(acc[2], ap, *(const unsigned long long*)(wp + 4));
            fma_x2(acc[3], ap, *(const unsigned long long*)(wp + 6));
        }
#pragma unroll
        for (int i = 0; i < 4; i++) {
            float lo, hi; unpack_x2(acc[i], lo, hi);
            int n = n0 + h * 8 + 2 * i;
            g_P[(size_t)(ks * 512 + n) * 128 + b]     = lo;
            g_P[(size_t)(ks * 512 + n + 1) * 128 + b] = hi;
        }
    }
    grid_sync(1);

    // ---------- phase 2.5: h1 = relu(sum_ks P + b1) ----
    if (tid < 128) {
        int idx = c * 128 + tid;
        const float4* P4 = (const float4*)g_P;
        float4 s0 = P4[idx], s1 = P4[16384 + idx];
        float4 s2 = P4[32768 + idx], s3 = P4[49152 + idx];
        float bb = b1[idx >> 5];
        float4 r;
        r.x = fmaxf(s0.x + s1.x + s2.x + s3.x + bb, 0.f);
        r.y = fmaxf(s0.y + s1.y + s2.y + s3.y + bb, 0.f);
        r.z = fmaxf(s0.z + s1.z + s2.z + s3.z + bb, 0.f);
        r.w = fmaxf(s0.w + s1.w + s2.w + s3.w + bb, 0.f);
        ((float4*)g_h1)[idx] = r;
    }
    grid_sync(2);

    // ---------- phase 3: h2 partials (8n x 128k, 4-way split-K) ----
    {
        const int n0 = (c >> 2) * 8, k0 = (c & 3) * 128, ks = c & 3;
        if (tid < 128) {
#pragma unroll
            for (int nn = 0; nn < 8; nn++)
                smw[tid * 10 + nn] = W2[(size_t)(n0 + nn) * 512 + k0 + tid];
        }
        __syncthreads();
        unsigned long long acc[2] = {0ull, 0ull};
#pragma unroll 16
        for (int kk = 0; kk < 128; kk++) {
            unsigned long long ap = dup_f32(g_h1[(size_t)(k0 + kk) * 128 + b]);
            const float* wp = &smw[kk * 10 + h * 4];
            fma_x2(acc[0], ap, *(const unsigned long long*)(wp + 0));
            fma_x2(acc[1], ap, *(const unsigned long long*)(wp + 2));
        }
#pragma unroll
        for (int i = 0; i < 2; i++) {
            float lo, hi; unpack_x2(acc[i], lo, hi);
            int n = n0 + h * 4 + 2 * i;
            g_P2[(size_t)(ks * 256 + n) * 128 + b]     = lo;
            g_P2[(size_t)(ks * 256 + n + 1) * 128 + b] = hi;
        }
    }
    grid_sync(3);

    // ---------- phase 3.5: h2 = relu(sum_ks P2 + b2) ----
    if (tid < 64) {
        int idx = c * 64 + tid;
        const float4* P4 = (const float4*)g_P2;
        float4 s0 = P4[idx], s1 = P4[8192 + idx];
        float4 s2 = P4[16384 + idx], s3 = P4[24576 + idx];
        float bb = b2[idx >> 5];
        float4 r;
        r.x = fmaxf(s0.x + s1.x + s2.x + s3.x + bb, 0.f);
        r.y = fmaxf(s0.y + s1.y + s2.y + s3.y + bb, 0.f);
        r.z = fmaxf(s0.z + s1.z + s2.z + s3.z + bb, 0.f);
        r.w = fmaxf(s0.w + s1.w + s2.w + s3.w + bb, 0.f);
        ((float4*)g_h2)[idx] = r;
    }
    grid_sync(4);

    // ---------- phase 4: final 2-wide layer, CTA 0 only ----
    if (c == 0) {
        smw[tid]       = W3[tid];
        smw[256 + tid] = W3[256 + tid];
        __syncthreads();
        if (tid < 128) {
            float a0 = 0.f, a1 = 0.f;
#pragma unroll 16
            for (int k = 0; k < 256; k++) {
                float hh = g_h2[k * 128 + tid];
                a0 += hh * smw[k];
                a1 += hh * smw[256 + k];
            }
            ((float2*)out)[tid] = make_float2(a0 + b3[0], a1 + b3[1]);
        }
    }
}

// ===========================================================================
extern "C" void kernel_launch(void* const* d_in, const int* in_sizes, int n_in,
                              void* d_out, int out_size) {
    const float* input = (const float*)d_in[0];
    const float* kW = (const float*)d_in[1];
    // d_in[2] = kb: constant score shift per batch -> cancels in softmax
    const float* vW = (const float*)d_in[3];
    const float* vb = (const float*)d_in[4];
    const float* qW = (const float*)d_in[5];
    const float* qb = (const float*)d_in[6];
    const float* W1 = (const float*)d_in[7];
    const float* b1 = (const float*)d_in[8];
    const float* W2 = (const float*)d_in[9];
    const float* b2 = (const float*)d_in[10];
    const float* W3 = (const float*)d_in[11];
    const float* b3 = (const float*)d_in[12];
    float* out = (float*)d_out;

    k0_kernel<<<64, 256>>>(kW, qW, qb);
    attn_kernel<<<256, 256>>>(input);
    mlp_kernel<<<128, 256>>>(vW, vb, W1, b1, W2, b2, W3, b3, out);
}

// round 8
// speedup vs baseline: 1.8581x; 1.3035x over previous
#include <cuda_runtime.h>
#include <cuda_bf16.h>
#include <cstdint>
#include <math.h>

// ---------------------------------------------------------------------------
// SimpleModelQ collapsed, SINGLE persistent kernel (+ counter-reset memset):
//   qk[b] = (M @ archi[b] + c) / sqrt(258),  M = kW^T qW, c = kW^T qb
//   (q.kb score shift is constant per batch -> cancels in softmax; kb unused)
//   fbar[b] = softmax(qk[b].feats[b,s])-weighted mean of feats (255-dim)
//   res = vW@fbar+vb; h1=relu(W1@res+b1); h2=relu(W2@h1+b2); out=W3@h2+b3
// 256 CTAs x 256 thr, launch_bounds(256,2) -> all co-resident -> grid syncs.
// ---------------------------------------------------------------------------

#define S_     1024
#define LAST_  258
#define FEAT_  255
#define NCTA_  256

// ---- device scratch ----
__device__ float4 g_qkp[64 * 256];      // k0 stage-1 partials
__device__ float4 g_qkp2[8 * 256];      // k0 stage-2 partials
__device__ float  g_u[256 * 256];       // per (b,half) unnormalized sums
__device__ float2 g_ml[256];            // per (b,half) (m, l)
__device__ float  g_fbarT[256 * 128];   // k-major [f][b] (row 255 unused)
__device__ float  g_res[1024 * 128];
__device__ float  g_P[8 * 512 * 128];   // h1 partials, 8-way split-K
__device__ float  g_h1[512 * 128];
__device__ float  g_P2[8 * 256 * 128];  // h2 partials, 8-way split-K
__device__ float  g_h2[256 * 128];
__device__ int    g_sync[16];           // reset by memset node each launch

__device__ __forceinline__ unsigned long long dup_f32(float a) {
    unsigned long long r;
    asm("mov.b64 %0, {%1, %1};" : "=l"(r) : "f"(a));
    return r;
}
__device__ __forceinline__ void fma_x2(unsigned long long& acc,
                                       unsigned long long a, unsigned long long w) {
    asm("fma.rn.f32x2 %0, %1, %2, %0;" : "+l"(acc) : "l"(a), "l"(w));
}
__device__ __forceinline__ void mul_x2(unsigned long long& d, unsigned long long a,
                                       unsigned long long b) {
    asm("mul.rn.f32x2 %0, %1, %2;" : "=l"(d) : "l"(a), "l"(b));
}
__device__ __forceinline__ void unpack_x2(unsigned long long v, float& lo, float& hi) {
    asm("mov.b64 {%0, %1}, %2;" : "=f"(lo), "=f"(hi) : "l"(v));
}

__device__ __forceinline__ void gsync(int i) {
    __syncthreads();
    if (threadIdx.x == 0) {
        __threadfence();
        atomicAdd(&g_sync[i], 1);
        while (*(volatile int*)&g_sync[i] < NCTA_) { }
        __threadfence();
    }
    __syncthreads();
}

__global__ void __launch_bounds__(256, 2)
fused_kernel(const float* __restrict__ input,
             const float* __restrict__ kW, const float* __restrict__ qW,
             const float* __restrict__ qb,
             const float* __restrict__ vW, const float* __restrict__ vb,
             const float* __restrict__ W1, const float* __restrict__ b1,
             const float* __restrict__ W2, const float* __restrict__ b2,
             const float* __restrict__ W3, const float* __restrict__ b3,
             float* __restrict__ out) {
    __shared__ float qk[256];
    __shared__ float red[8 * 256];
    __shared__ float2 mlw[8];
    __shared__ float sw[64];
    __shared__ __align__(16) float smw[256 * 18];

    const int c    = blockIdx.x;
    const int tid  = threadIdx.x;
    const int lane = tid & 31, w = tid >> 5;
    const int ab = c >> 1, ahalf = c & 1;           // attention mapping
    const float* gbase = input + (size_t)ab * S_ * LAST_;
    const float* pbase = gbase + (size_t)(ahalf * 512) * LAST_ + lane * 2;

    // ---------- prefetch attention chunk 0 (overlaps k0 phase) ----------
    unsigned long long xA[4][4], xB[4][4];
    {
        const float* rp = pbase + (size_t)(w * 4) * LAST_;
#pragma unroll
        for (int i = 0; i < 4; i++)
#pragma unroll
            for (int j = 0; j < 4; j++)
                xA[i][j] = *(const unsigned long long*)(rp + (size_t)i * LAST_ + j * 64);
    }
    const float ar0 = gbase[FEAT_ + 0];
    const float ar1 = gbase[FEAT_ + 1];
    const float ar2 = gbase[FEAT_ + 2];

    // ---------- phase 0: k0 partials (CTAs 0..63, 16 h-rows each) ----------
    if (c < 64) {
        const int h0 = c * 16;
        if (tid < 64) {
            int h = h0 + (tid >> 2), k = tid & 3;
            sw[tid] = (k < 3) ? qW[h * 3 + k] : qb[h];
        }
        __syncthreads();
        float m0 = 0.f, m1 = 0.f, m2 = 0.f, cc2 = 0.f;
        if (tid < FEAT_) {
#pragma unroll
            for (int i = 0; i < 16; i++) {
                float kv = kW[(size_t)(h0 + i) * FEAT_ + tid];
                m0 += kv * sw[i * 4 + 0];
                m1 += kv * sw[i * 4 + 1];
                m2 += kv * sw[i * 4 + 2];
                cc2 += kv * sw[i * 4 + 3];
            }
        }
        g_qkp[c * 256 + tid] = make_float4(m0, m1, m2, cc2);
    }
    gsync(0);

    // ---------- phase 0b: stage-2 merge (CTAs 0..7, 8 blocks each) ----------
    if (c < 8) {
        float4 s = make_float4(0.f, 0.f, 0.f, 0.f);
#pragma unroll
        for (int p = 0; p < 8; p++) {
            float4 v = g_qkp[(c * 8 + p) * 256 + tid];
            s.x += v.x; s.y += v.y; s.z += v.z; s.w += v.w;
        }
        g_qkp2[c * 256 + tid] = s;
    }
    gsync(1);

    // ---------- qk vector for this CTA's batch ----------
    {
        float4 s = make_float4(0.f, 0.f, 0.f, 0.f);
#pragma unroll
        for (int p = 0; p < 8; p++) {
            float4 v = g_qkp2[p * 256 + tid];
            s.x += v.x; s.y += v.y; s.z += v.z; s.w += v.w;
        }
        float val = (s.x * ar0 + s.y * ar1 + s.z * ar2 + s.w) * rsqrtf(258.0f);
        qk[tid] = (tid < FEAT_) ? val : 0.f;
    }
    __syncthreads();

    unsigned long long q2[4];
#pragma unroll
    for (int j = 0; j < 4; j++)
        q2[j] = *(const unsigned long long*)(qk + j * 64 + lane * 2);

    // ---------- attention mainloop: warp-local softmax, no barriers ----------
    float m_w = -INFINITY, l_w = 0.f;
    unsigned long long acc[4] = {0ull, 0ull, 0ull, 0ull};

    auto loadc = [&](unsigned long long (&x)[4][4], int ch) {
        const float* rp = pbase + (size_t)(ch * 32 + w * 4) * LAST_;
#pragma unroll
        for (int i = 0; i < 4; i++)
#pragma unroll
            for (int j = 0; j < 4; j++)
                x[i][j] = *(const unsigned long long*)(rp + (size_t)i * LAST_ + j * 64);
    };
    auto process = [&](unsigned long long (&x)[4][4]) {
        float v[4];
#pragma unroll
        for (int i = 0; i < 4; i++) {
            unsigned long long va = 0ull;
#pragma unroll
            for (int j = 0; j < 4; j++) fma_x2(va, x[i][j], q2[j]);
            float lo, hi; unpack_x2(va, lo, hi);
            v[i] = lo + hi;
        }
#pragma unroll
        for (int o = 16; o; o >>= 1) {
#pragma unroll
            for (int i = 0; i < 4; i++)
                v[i] += __shfl_xor_sync(0xffffffffu, v[i], o);
        }
        float mc = fmaxf(fmaxf(v[0], v[1]), fmaxf(v[2], v[3]));
        float mnew  = fmaxf(m_w, mc);
        float alpha = __expf(m_w - mnew);
        float p0 = __expf(v[0] - mnew), p1 = __expf(v[1] - mnew);
        float p2 = __expf(v[2] - mnew), p3 = __expf(v[3] - mnew);
        l_w = l_w * alpha + (p0 + p1) + (p2 + p3);
        m_w = mnew;
        unsigned long long ap = dup_f32(alpha);
#pragma unroll
        for (int j = 0; j < 4; j++) mul_x2(acc[j], acc[j], ap);
        unsigned long long pp0 = dup_f32(p0), pp1 = dup_f32(p1);
        unsigned long long pp2 = dup_f32(p2), pp3 = dup_f32(p3);
#pragma unroll
        for (int j = 0; j < 4; j++) {
            fma_x2(acc[j], pp0, x[0][j]);
            fma_x2(acc[j], pp1, x[1][j]);
            fma_x2(acc[j], pp2, x[2][j]);
            fma_x2(acc[j], pp3, x[3][j]);
        }
    };

    for (int cc = 0; cc < 8; cc++) {
        loadc(xB, 2 * cc + 1);
        process(xA);
        if (cc < 7) loadc(xA, 2 * cc + 2);
        process(xB);
    }

    // ---------- attention epilogue: merge 8 warps -> per-CTA (M, L, u) ----------
#pragma unroll
    for (int j = 0; j < 4; j++)
        *(unsigned long long*)(red + w * 256 + j * 64 + lane * 2) = acc[j];
    if (lane == 0) mlw[w] = make_float2(m_w, l_w);
    __syncthreads();
    {
        float M = -INFINITY;
#pragma unroll
        for (int ww = 0; ww < 8; ww++) M = fmaxf(M, mlw[ww].x);
        float L = 0.f, u = 0.f;
#pragma unroll
        for (int ww = 0; ww < 8; ww++) {
            float e = __expf(mlw[ww].x - M);
            L += e * mlw[ww].y;
            u += e * red[ww * 256 + tid];
        }
        g_u[(size_t)c * 256 + tid] = u;
        if (tid == 0) g_ml[c] = make_float2(M, L);
    }
    gsync(2);

    // ---------- fbar: CTA = feature f, thread = batch b (coalesced writes) ----
    if (c < FEAT_ && tid < 128) {
        const int f = c, b = tid;
        float2 ml0 = g_ml[b * 2 + 0];
        float2 ml1 = g_ml[b * 2 + 1];
        float M  = fmaxf(ml0.x, ml1.x);
        float e0 = __expf(ml0.x - M);
        float e1 = __expf(ml1.x - M);
        float invL = 1.0f / (e0 * ml0.y + e1 * ml1.y);
        float u0 = g_u[(size_t)(b * 2 + 0) * 256 + f];
        float u1 = g_u[(size_t)(b * 2 + 1) * 256 + f];
        g_fbarT[f * 128 + b] = (e0 * u0 + e1 * u1) * invL;
    }
    gsync(3);

    const int b = tid & 127, h = tid >> 7;

    // ---------- phase 1: res = vW @ fbar + vb  (4 n per CTA, K=256) ----------
    {
        const int n0 = c * 4;
#pragma unroll
        for (int nn = 0; nn < 4; nn++)
            smw[tid * 6 + nn] = (tid < FEAT_) ? vW[(size_t)(n0 + nn) * FEAT_ + tid] : 0.f;
        __syncthreads();
        unsigned long long a1 = 0ull;
#pragma unroll 16
        for (int kk = 0; kk < 256; kk++) {
            unsigned long long ap = dup_f32(g_fbarT[kk * 128 + b]);
            fma_x2(a1, ap, *(const unsigned long long*)&smw[kk * 6 + h * 2]);
        }
        float lo, hi; unpack_x2(a1, lo, hi);
        int n = n0 + h * 2;
        g_res[(size_t)n * 128 + b]       = lo + vb[n];
        g_res[(size_t)(n + 1) * 128 + b] = hi + vb[n + 1];
    }
    gsync(4);

    // ---------- phase 2: h1 partials (32 tiles x 16n, 8-way split-K) ----------
    {
        const int n0 = (c >> 3) * 16, ks = c & 7, k0 = ks * 128;
        if (tid < 128) {
#pragma unroll
            for (int nn = 0; nn < 16; nn++)
                smw[tid * 18 + nn] = W1[(size_t)(n0 + nn) * 1024 + k0 + tid];
        }
        __syncthreads();
        unsigned long long a4[4] = {0ull, 0ull, 0ull, 0ull};
#pragma unroll 16
        for (int kk = 0; kk < 128; kk++) {
            unsigned long long ap = dup_f32(g_res[(size_t)(k0 + kk) * 128 + b]);
            const float* wp = &smw[kk * 18 + h * 8];
            fma_x2(a4[0], ap, *(const unsigned long long*)(wp + 0));
            fma_x2(a4[1], ap, *(const unsigned long long*)(wp + 2));
            fma_x2(a4[2], ap, *(const unsigned long long*)(wp + 4));
            fma_x2(a4[3], ap, *(const unsigned long long*)(wp + 6));
        }
#pragma unroll
        for (int i = 0; i < 4; i++) {
            float lo, hi; unpack_x2(a4[i], lo, hi);
            int n = n0 + h * 8 + 2 * i;
            g_P[(size_t)(ks * 512 + n) * 128 + b]     = lo;
            g_P[(size_t)(ks * 512 + n + 1) * 128 + b] = hi;
        }
        __syncthreads();
    }
    gsync(5);

    // ---------- phase 2.5: h1 = relu(sum of 8 splits + b1) ----------
    if (tid < 64) {
        int idx = c * 64 + tid;                       // 16384 float4 total
        const float4* P4 = (const float4*)g_P;
        float4 r = make_float4(0.f, 0.f, 0.f, 0.f);
#pragma unroll
        for (int s = 0; s < 8; s++) {
            float4 v = P4[(size_t)s * 16384 + idx];
            r.x += v.x; r.y += v.y; r.z += v.z; r.w += v.w;
        }
        float bb = b1[idx >> 5];
        r.x = fmaxf(r.x + bb, 0.f); r.y = fmaxf(r.y + bb, 0.f);
        r.z = fmaxf(r.z + bb, 0.f); r.w = fmaxf(r.w + bb, 0.f);
        ((float4*)g_h1)[idx] = r;
    }
    gsync(6);

    // ---------- phase 3: h2 partials (32 tiles x 8n, 8-way split-K) ----------
    {
        const int n0 = (c >> 3) * 8, ks = c & 7, k0 = ks * 64;
        if (tid < 64) {
#pragma unroll
            for (int nn = 0; nn < 8; nn++)
                smw[tid * 10 + nn] = W2[(size_t)(n0 + nn) * 512 + k0 + tid];
        }
        __syncthreads();
        unsigned long long a2[2] = {0ull, 0ull};
#pragma unroll 16
        for (int kk = 0; kk < 64; kk++) {
            unsigned long long ap = dup_f32(g_h1[(size_t)(k0 + kk) * 128 + b]);
            const float* wp = &smw[kk * 10 + h * 4];
            fma_x2(a2[0], ap, *(const unsigned long long*)(wp + 0));
            fma_x2(a2[1], ap, *(const unsigned long long*)(wp + 2));
        }
#pragma unroll
        for (int i = 0; i < 2; i++) {
            float lo, hi; unpack_x2(a2[i], lo, hi);
            int n = n0 + h * 4 + 2 * i;
            g_P2[(size_t)(ks * 256 + n) * 128 + b]     = lo;
            g_P2[(size_t)(ks * 256 + n + 1) * 128 + b] = hi;
        }
        __syncthreads();
    }
    gsync(7);

    // ---------- phase 3.5: h2 = relu(sum of 8 splits + b2) ----------
    if (tid < 32) {
        int idx = c * 32 + tid;                       // 8192 float4 total
        const float4* P4 = (const float4*)g_P2;
        float4 r = make_float4(0.f, 0.f, 0.f, 0.f);
#pragma unroll
        for (int s = 0; s < 8; s++) {
            float4 v = P4[(size_t)s * 8192 + idx];
            r.x += v.x; r.y += v.y; r.z += v.z; r.w += v.w;
        }
        float bb = b2[idx >> 5];
        r.x = fmaxf(r.x + bb, 0.f); r.y = fmaxf(r.y + bb, 0.f);
        r.z = fmaxf(r.z + bb, 0.f); r.w = fmaxf(r.w + bb, 0.f);
        ((float4*)g_h2)[idx] = r;
    }
    gsync(8);

    // ---------- phase 4: final 2-wide layer, CTA 0 only ----------
    if (c == 0) {
        smw[tid]       = W3[tid];
        smw[256 + tid] = W3[256 + tid];
        __syncthreads();
        if (tid < 128) {
            float o0 = 0.f, o1 = 0.f;
#pragma unroll 16
            for (int k = 0; k < 256; k++) {
                float hh = g_h2[k * 128 + tid];
                o0 += hh * smw[k];
                o1 += hh * smw[256 + k];
            }
            ((float2*)out)[tid] = make_float2(o0 + b3[0], o1 + b3[1]);
        }
    }
}

// ===========================================================================
extern "C" void kernel_launch(void* const* d_in, const int* in_sizes, int n_in,
                              void* d_out, int out_size) {
    const float* input = (const float*)d_in[0];
    const float* kW = (const float*)d_in[1];
    // d_in[2] = kb: constant score shift per batch -> cancels in softmax
    const float* vW = (const float*)d_in[3];
    const float* vb = (const float*)d_in[4];
    const float* qW = (const float*)d_in[5];
    const float* qb = (const float*)d_in[6];
    const float* W1 = (const float*)d_in[7];
    const float* b1 = (const float*)d_in[8];
    const float* W2 = (const float*)d_in[9];
    const float* b2 = (const float*)d_in[10];
    const float* W3 = (const float*)d_in[11];
    const float* b3 = (const float*)d_in[12];
    float* out = (float*)d_out;

    void* p_sync = nullptr;
    cudaGetSymbolAddress(&p_sync, g_sync);
    cudaMemsetAsync(p_sync, 0, 16 * sizeof(int));   // reset grid-sync counters

    fused_kernel<<<NCTA_, 256>>>(input, kW, qW, qb, vW, vb,
                                 W1, b1, W2, b2, W3, b3, out);
}